// round 5
// baseline (speedup 1.0000x reference)
#include <cuda_runtime.h>
#include <math.h>

#define N_TOK 4096
#define D_DIM 2048
#define N_EXP 8
#define TOPK  2
#define CAP   512
#define PITCH 1028                 // padded smem row (floats)
#define BLK   512
#define GRID  128                  // 1 block/SM, single wave guaranteed
#define TPW   2                    // tokens per warp: 128*16*2 = 4096

__device__ int g_choice[N_TOK * TOPK];
__device__ unsigned int g_bar;     // epoch barrier counter (never reset)

__global__ __launch_bounds__(BLK) void k_fused(
        const float* __restrict__ x,
        const float* __restrict__ W,
        float* __restrict__ out) {
    __shared__ float wt[N_EXP * PITCH];   // 32.9 KB
    __shared__ int warp_sums[16];

    int tid  = threadIdx.x;
    int lane = tid & 31;
    int wrp  = tid >> 5;
    int bid  = blockIdx.x;
    int t0   = (bid * 16 + wrp) * TPW;

    const float4* x4 = reinterpret_cast<const float4*>(x);
    float acc0[N_EXP] = {0,0,0,0,0,0,0,0};
    float acc1[N_EXP] = {0,0,0,0,0,0,0,0};

    // ---------------- Phase 1: logits GEMM ----------------
    for (int p = 0; p < 2; p++) {
        // stage W[p*1024 .. +1024) transposed: wt[e][d]
        #pragma unroll
        for (int idx = tid; idx < 1024 * N_EXP; idx += BLK) {
            int dl = idx >> 3;
            int e  = idx & 7;
            wt[e * PITCH + dl] = W[(p * 1024 + dl) * N_EXP + e];
        }
        __syncthreads();

        #pragma unroll 4
        for (int i = 0; i < 8; i++) {
            int j = i * 32 + lane;      // float4 idx within phase [0,256)
            float4 xv0 = __ldcs(&x4[(size_t)t0       * (D_DIM/4) + p * 256 + j]);
            float4 xv1 = __ldcs(&x4[(size_t)(t0 + 1) * (D_DIM/4) + p * 256 + j]);
            #pragma unroll
            for (int e = 0; e < N_EXP; e++) {
                float4 w = *reinterpret_cast<const float4*>(&wt[e * PITCH + j * 4]);
                acc0[e] += xv0.x * w.x + xv0.y * w.y + xv0.z * w.z + xv0.w * w.w;
                acc1[e] += xv1.x * w.x + xv1.y * w.y + xv1.z * w.z + xv1.w * w.w;
            }
        }
        __syncthreads();
    }

    #pragma unroll
    for (int e = 0; e < N_EXP; e++) {
        #pragma unroll
        for (int off = 16; off > 0; off >>= 1) {
            acc0[e] += __shfl_xor_sync(0xffffffffu, acc0[e], off);
            acc1[e] += __shfl_xor_sync(0xffffffffu, acc1[e], off);
        }
    }

    if (lane == 0) {
        float* gate = out + (size_t)N_TOK * N_EXP * CAP;
        float* idxf = gate + N_TOK * TOPK;
        #pragma unroll
        for (int t = 0; t < TPW; t++) {
            float* a = t ? acc1 : acc0;
            int tok = t0 + t;
            float best = -INFINITY, sec = -INFINITY;
            int bi = 0, si = 0;
            #pragma unroll
            for (int e = 0; e < N_EXP; e++) {
                float v = a[e];
                if (v > best)     { sec = best; si = bi; best = v; bi = e; }
                else if (v > sec) { sec = v;    si = e; }
            }
            float g0 = 1.0f / (1.0f + expf(sec - best));
            gate[tok * 2 + 0] = g0;
            gate[tok * 2 + 1] = 1.0f - g0;
            idxf[tok * 2 + 0] = (float)bi;
            idxf[tok * 2 + 1] = (float)si;
            g_choice[tok * 2 + 0] = bi;
            g_choice[tok * 2 + 1] = si;
        }
    }

    // ---------------- Phase 2: zero-fill dispatcher chunk ----------------
    {
        float4* z4 = reinterpret_cast<float4*>(out);
        size_t base = (size_t)bid * 32768;      // 4.19M f4 / 128 blocks
        const float4 zero = make_float4(0.f, 0.f, 0.f, 0.f);
        #pragma unroll 8
        for (int q = 0; q < 64; q++)
            __stcs(&z4[base + (size_t)q * BLK + tid], zero);
    }

    // ---------------- Global barrier (epoch-based, replay-safe) ----------
    __threadfence();
    __syncthreads();
    if (tid == 0) {
        unsigned int old = atomicAdd(&g_bar, 1u);
        unsigned int target = (old / GRID) * GRID + GRID;
        while (true) {
            unsigned int v = atomicAdd(&g_bar, 0u);   // acquire-ish read
            if (v >= target) break;
            __nanosleep(64);
        }
    }
    __syncthreads();
    __threadfence();

    // ---------------- Phase 3: scan + scatter (blocks 0..15) -------------
    if (bid >= 16) return;
    int k = bid >> 3;
    int e = bid & 7;

    int n0 = tid * 8;                 // 512 threads * 8 tokens = 4096
    int flags[8];
    int localex[8];
    int s = 0;
    #pragma unroll
    for (int j = 0; j < 8; j++) {
        flags[j]   = (g_choice[(n0 + j) * 2 + k] == e) ? 1 : 0;
        localex[j] = s;
        s += flags[j];
    }

    int inc = s;
    #pragma unroll
    for (int off = 1; off < 32; off <<= 1) {
        int v = __shfl_up_sync(0xffffffffu, inc, off);
        if (lane >= off) inc += v;
    }
    if (lane == 31) warp_sums[wrp] = inc;
    __syncthreads();

    if (wrp == 0 && lane < 16) {
        int v = warp_sums[lane];
        int winc = v;
        #pragma unroll
        for (int off = 1; off < 16; off <<= 1) {
            int u = __shfl_up_sync(0x0000ffffu, winc, off);
            if (lane >= off) winc += u;
        }
        warp_sums[lane] = winc - v;   // exclusive warp offsets
    }
    __syncthreads();

    int thread_prefix = warp_sums[wrp] + (inc - s);

    #pragma unroll
    for (int j = 0; j < 8; j++) {
        if (flags[j]) {
            int pri = thread_prefix + localex[j] + 1;   // 1-based priority
            if (pri <= CAP)
                out[(size_t)(n0 + j) * (N_EXP * CAP) + e * CAP + (pri - 1)] = 1.0f;
        }
    }
}

// ---------------------------------------------------------------------------
extern "C" void kernel_launch(void* const* d_in, const int* in_sizes, int n_in,
                              void* d_out, int out_size) {
    const float* x = (const float*)d_in[0];   // [4096, 2048]
    const float* W = (const float*)d_in[1];   // [2048, 8]
    float* out = (float*)d_out;

    k_fused<<<GRID, BLK>>>(x, W, out);
}